// round 14
// baseline (speedup 1.0000x reference)
#include <cuda_runtime.h>
#include <cstdint>

#define TSTEPS 512
#define H 20
#define NB 2            // batches per 4-lane group
#define NTHREADS 128    // 4 warps -> one per SMSP (wid%4)
#define NBLOCKS 128     // 128 * 4 * 8 * 2 = 8192 batches; 1 block/SM
#define SUBSTRIDE 2008  // floats per sub weight copy (pad -> distinct 16B phases)

typedef unsigned long long u64;

__device__ __forceinline__ void ffma2(u64& acc, u64 a, u64 b) {
    asm("fma.rn.f32x2 %0, %1, %2, %0;" : "+l"(acc) : "l"(a), "l"(b));
}
__device__ __forceinline__ u64 pack2(float lo, float hi) {
    u64 r; asm("mov.b64 %0, {%1, %2};" : "=l"(r) : "f"(lo), "f"(hi)); return r;
}
__device__ __forceinline__ float2 unpack2(u64 v) {
    float2 r; asm("mov.b64 {%0, %1}, %2;" : "=f"(r.x), "=f"(r.y) : "l"(v)); return r;
}
// 5-op tanh: 1 - 2/(e^{2x}+1); finite for all finite x (drain-safe).
__device__ __forceinline__ float tanh_fast(float x) {
    float e;
    asm("ex2.approx.f32 %0, %1;" : "=f"(e) : "f"(x * 2.8853900817779268f));
    float rr;
    asm("rcp.approx.f32 %0, %1;" : "=f"(rr) : "f"(e + 1.0f));
    return fmaf(-2.0f, rr, 1.0f);
}

// 4-lane butterfly all-gather: own 5 h values -> all 20, k-pair packed,
// per-lane block order [sub, sub^1, sub^2, sub^3] (weights pre-permuted).
__device__ __forceinline__ void gather20(const float v[5], u64 hp[10]) {
    float a[10];
#pragma unroll
    for (int i = 0; i < 5; i++) {
        a[i]     = v[i];
        a[5 + i] = __shfl_xor_sync(0xffffffffu, v[i], 1);
    }
#pragma unroll
    for (int q = 0; q < 5; q++) hp[q] = pack2(a[2 * q], a[2 * q + 1]);
    float b[10];
#pragma unroll
    for (int i = 0; i < 10; i++) b[i] = __shfl_xor_sync(0xffffffffu, a[i], 2);
#pragma unroll
    for (int q = 0; q < 5; q++) hp[5 + q] = pack2(b[2 * q], b[2 * q + 1]);
}

__global__ __launch_bounds__(NTHREADS)
void rnn3_kernel(
    const float* __restrict__ x,
    const float* __restrict__ w_ih0, const float* __restrict__ w_hh0,
    const float* __restrict__ b_ih0, const float* __restrict__ b_hh0,
    const float* __restrict__ w_ih1, const float* __restrict__ w_hh1,
    const float* __restrict__ b_ih1, const float* __restrict__ b_hh1,
    const float* __restrict__ w_ih2, const float* __restrict__ w_hh2,
    const float* __restrict__ b_ih2, const float* __restrict__ b_hh2,
    const float* __restrict__ fc_w, const float* __restrict__ fc_b,
    float* __restrict__ out)
{
    // per-sub permuted weight copies: wp[sub][m][j][k], column k maps to
    // original column 5*(sub ^ (k/5)) + k%5.
    // m: 0=w_hh0 1=w_ih1 2=w_hh1 3=w_ih2 4=w_hh2
    __shared__ __align__(16) float wp[4 * SUBSTRIDE];

    const int tid = threadIdx.x;
    for (int idx = tid; idx < 4 * 2000; idx += NTHREADS) {
        int sb  = idx / 2000;
        int rem = idx % 2000;
        int m   = rem / 400;
        int r   = rem % 400;
        int j   = r / H;
        int k   = r % H;
        int oc  = 5 * (sb ^ (k / 5)) + (k % 5);
        const float* src = (m == 0) ? w_hh0 : (m == 1) ? w_ih1 :
                           (m == 2) ? w_hh1 : (m == 3) ? w_ih2 : w_hh2;
        wp[sb * SUBSTRIDE + (m * H + j) * H + k] = src[j * H + oc];
    }
    __syncthreads();

    const int lane = tid & 31;
    const int warp = tid >> 5;            // 0..3 -> SMSP 0..3
    const int gi   = lane >> 2;
    const int sub  = lane & 3;
    const int j0   = sub * 5;
    const int b0   = blockIdx.x * 64 + warp * 16 + gi;   // batch slot 0
    const int b1   = b0 + 8;                              // batch slot 1

    const float* wsub = wp + sub * SUBSTRIDE + j0 * H;

    float bias0[5], bias1[5], bias2[5], wih0r[5];
#pragma unroll
    for (int jj = 0; jj < 5; jj++) {
        int j = j0 + jj;
        bias0[jj] = b_ih0[j] + b_hh0[j];
        bias1[jj] = b_ih1[j] + b_hh1[j];
        bias2[jj] = b_ih2[j] + b_hh2[j];
        wih0r[jj] = w_ih0[j];
    }

    const float* xrow0 = x + (size_t)b0 * TSTEPS;
    const float* xrow1 = x + (size_t)b1 * TSTEPS;

    // own-form persistent hidden state (registers only)
    float h0own[NB][5], h1own[NB][5], h2own[NB][5];
#pragma unroll
    for (int i = 0; i < NB; i++)
#pragma unroll
        for (int jj = 0; jj < 5; jj++) {
            h0own[i][jj] = 0.f; h1own[i][jj] = 0.f; h2own[i][jj] = 0.f;
        }

    float4 xq[NB];
#pragma unroll
    for (int i = 0; i < NB; i++) xq[i] = make_float4(0.f, 0.f, 0.f, 0.f);

    // Skewed pipeline: iteration s computes L0(s), L1(s-1), L2(s-2).
    // The three layer chains are mutually independent within an iteration
    // -> ~3x ready-instruction pool to hide LDS/shfl/MUFU latency at
    // 1 warp/SMSP. Only one gathered h-set live at a time (caps regs).
#pragma unroll 1
    for (int s = 0; s < TSTEPS + 2; s++) {
        if (((s & 3) == 0) && (s < TSTEPS)) {
            xq[0] = __ldg((const float4*)(xrow0 + s));
            xq[1] = __ldg((const float4*)(xrow1 + s));
        }
        const int ph = s & 3;
        float xv[NB];
#pragma unroll
        for (int i = 0; i < NB; i++)
            xv[i] = (ph == 0) ? xq[i].x : (ph == 1) ? xq[i].y :
                    (ph == 2) ? xq[i].z : xq[i].w;

        u64 g[NB][10];
        u64 acc1[NB][5];

        // ===== phase A: gather h0(s-1); L0(s); L1 input-half (s-1) =====
#pragma unroll
        for (int i = 0; i < NB; i++) gather20(h0own[i], g[i]);
        {
            u64 acc0[NB][5];
#pragma unroll
            for (int i = 0; i < NB; i++)
#pragma unroll
                for (int jj = 0; jj < 5; jj++)
                    acc0[i][jj] = pack2(fmaf(xv[i], wih0r[jj], bias0[jj]), 0.f);
#pragma unroll
            for (int q = 0; q < 5; q++)
#pragma unroll
                for (int jj = 0; jj < 5; jj++) {
                    ulonglong2 w2 = ((const ulonglong2*)(wsub + jj * H))[q];       // m0
#pragma unroll
                    for (int i = 0; i < NB; i++) {
                        ffma2(acc0[i][jj], g[i][2*q],   w2.x);
                        ffma2(acc0[i][jj], g[i][2*q+1], w2.y);
                    }
                }
#pragma unroll
            for (int i = 0; i < NB; i++)
#pragma unroll
                for (int jj = 0; jj < 5; jj++) {
                    float2 p = unpack2(acc0[i][jj]);
                    h0own[i][jj] = tanh_fast(p.x + p.y);     // h0(s)
                }
        }
        // L1 input-half: acc1 = bias1 + Wih1 @ h0(s-1)  (reuses gathered g)
#pragma unroll
        for (int i = 0; i < NB; i++)
#pragma unroll
            for (int jj = 0; jj < 5; jj++) acc1[i][jj] = pack2(bias1[jj], 0.f);
#pragma unroll
        for (int q = 0; q < 5; q++)
#pragma unroll
            for (int jj = 0; jj < 5; jj++) {
                ulonglong2 w2 = ((const ulonglong2*)(wsub + 400 + jj * H))[q];     // m1
#pragma unroll
                for (int i = 0; i < NB; i++) {
                    ffma2(acc1[i][jj], g[i][2*q],   w2.x);
                    ffma2(acc1[i][jj], g[i][2*q+1], w2.y);
                }
            }

        // ===== phase B: gather h1(s-2); finish L1 -> h1(s-1); L2 input-half =====
#pragma unroll
        for (int i = 0; i < NB; i++) gather20(h1own[i], g[i]);
#pragma unroll
        for (int q = 0; q < 5; q++)
#pragma unroll
            for (int jj = 0; jj < 5; jj++) {
                ulonglong2 w2 = ((const ulonglong2*)(wsub + 800 + jj * H))[q];     // m2
#pragma unroll
                for (int i = 0; i < NB; i++) {
                    ffma2(acc1[i][jj], g[i][2*q],   w2.x);
                    ffma2(acc1[i][jj], g[i][2*q+1], w2.y);
                }
            }
        if (s >= 1) {   // retire acc1 -> h1(s-1); keep h1(-1)=0 at s=0
#pragma unroll
            for (int i = 0; i < NB; i++)
#pragma unroll
                for (int jj = 0; jj < 5; jj++) {
                    float2 p = unpack2(acc1[i][jj]);
                    h1own[i][jj] = tanh_fast(p.x + p.y);
                }
        }
        u64 acc2[NB][5];
#pragma unroll
        for (int i = 0; i < NB; i++)
#pragma unroll
            for (int jj = 0; jj < 5; jj++) acc2[i][jj] = pack2(bias2[jj], 0.f);
#pragma unroll
        for (int q = 0; q < 5; q++)
#pragma unroll
            for (int jj = 0; jj < 5; jj++) {
                ulonglong2 w2 = ((const ulonglong2*)(wsub + 1200 + jj * H))[q];    // m3
#pragma unroll
                for (int i = 0; i < NB; i++) {
                    ffma2(acc2[i][jj], g[i][2*q],   w2.x);
                    ffma2(acc2[i][jj], g[i][2*q+1], w2.y);
                }
            }

        // ===== phase C: gather h2(s-3); finish L2 -> h2(s-2) =====
#pragma unroll
        for (int i = 0; i < NB; i++) gather20(h2own[i], g[i]);
#pragma unroll
        for (int q = 0; q < 5; q++)
#pragma unroll
            for (int jj = 0; jj < 5; jj++) {
                ulonglong2 w2 = ((const ulonglong2*)(wsub + 1600 + jj * H))[q];    // m4
#pragma unroll
                for (int i = 0; i < NB; i++) {
                    ffma2(acc2[i][jj], g[i][2*q],   w2.x);
                    ffma2(acc2[i][jj], g[i][2*q+1], w2.y);
                }
            }
        if (s >= 2) {   // retire acc2 -> h2(s-2); keep h2(-1)=0 for s<2
#pragma unroll
            for (int i = 0; i < NB; i++)
#pragma unroll
                for (int jj = 0; jj < 5; jj++) {
                    float2 p = unpack2(acc2[i][jj]);
                    h2own[i][jj] = tanh_fast(p.x + p.y);
                }
        }
    }
    // after s = TSTEPS+1: h2own = h2(TSTEPS-1)

    // ===== FC epilogue: out[b] = h2 . fc_w + fc_b =====
    const float fb = __ldg(&fc_b[0]);
    const int bb[NB] = { b0, b1 };
#pragma unroll
    for (int i = 0; i < NB; i++) {
        float s = 0.f;
#pragma unroll
        for (int jj = 0; jj < 5; jj++)
            s += h2own[i][jj] * __ldg(&fc_w[j0 + jj]);
        s += __shfl_xor_sync(0xffffffffu, s, 1);
        s += __shfl_xor_sync(0xffffffffu, s, 2);
        if (sub == 0) out[bb[i]] = s + fb;
    }
}

extern "C" void kernel_launch(void* const* d_in, const int* in_sizes, int n_in,
                              void* d_out, int out_size) {
    (void)in_sizes; (void)n_in; (void)out_size;
    rnn3_kernel<<<NBLOCKS, NTHREADS>>>(
        (const float*)d_in[0],
        (const float*)d_in[1],  (const float*)d_in[2],
        (const float*)d_in[3],  (const float*)d_in[4],
        (const float*)d_in[5],  (const float*)d_in[6],
        (const float*)d_in[7],  (const float*)d_in[8],
        (const float*)d_in[9],  (const float*)d_in[10],
        (const float*)d_in[11], (const float*)d_in[12],
        (const float*)d_in[13], (const float*)d_in[14],
        (float*)d_out);
}

// round 15
// speedup vs baseline: 1.1147x; 1.1147x over previous
#include <cuda_runtime.h>
#include <cstdint>

#define TSTEPS 512
#define H 20
#define NTHREADS 128    // 4 warps -> one per SMSP (wid%4)
#define NBLOCKS 128     // 128 blocks * 64 batches = 8192; 1 block/SM, balanced

typedef unsigned long long u64;

__device__ __forceinline__ void ffma2(u64& acc, u64 a, u64 b) {
    asm("fma.rn.f32x2 %0, %1, %2, %0;" : "+l"(acc) : "l"(a), "l"(b));
}
__device__ __forceinline__ u64 pack2(float lo, float hi) {
    u64 r; asm("mov.b64 %0, {%1, %2};" : "=l"(r) : "f"(lo), "f"(hi)); return r;
}
__device__ __forceinline__ float2 unpack2(u64 v) {
    float2 r; asm("mov.b64 {%0, %1}, %2;" : "=f"(r.x), "=f"(r.y) : "l"(v)); return r;
}
// 5-op tanh: 1 - 2/(e^{2x}+1). ex2.approx+rcp.approx, abs err ~1e-7.
__device__ __forceinline__ float tanh_fast(float x) {
    float e;
    asm("ex2.approx.f32 %0, %1;" : "=f"(e) : "f"(x * 2.8853900817779268f));
    float rr;
    asm("rcp.approx.f32 %0, %1;" : "=f"(rr) : "f"(e + 1.0f));
    return fmaf(-2.0f, rr, 1.0f);
}

__global__ __launch_bounds__(NTHREADS)
void rnn3_kernel(
    const float* __restrict__ x,
    const float* __restrict__ w_ih0, const float* __restrict__ w_hh0,
    const float* __restrict__ b_ih0, const float* __restrict__ b_hh0,
    const float* __restrict__ w_ih1, const float* __restrict__ w_hh1,
    const float* __restrict__ b_ih1, const float* __restrict__ b_hh1,
    const float* __restrict__ w_ih2, const float* __restrict__ w_hh2,
    const float* __restrict__ b_ih2, const float* __restrict__ b_hh2,
    const float* __restrict__ fc_w, const float* __restrict__ fc_b,
    float* __restrict__ out)
{
    // Quad-interleaved permuted weights:
    //   wp[ ((m*5 + jj)*5 + q)*16 + sub*4 + e ]
    //     = W_m[ sub*5 + jj ][ 5*(sub ^ (k/5)) + k%5 ],  k = 4q + e
    // The 4 subs' quads for one (m,jj,q) sit in ONE 64-B span -> each weight
    // LDS.128 touches a single 128-B line -> 1 wavefront (was 4).
    // m: 0=w_hh0 1=w_ih1 2=w_hh1 3=w_ih2 4=w_hh2.  Total 2000 floats = 8 KB.
    __shared__ __align__(16) float wp[2000];

    const int tid = threadIdx.x;
    for (int idx = tid; idx < 2000; idx += NTHREADS) {
        int m   = idx / 400;
        int r   = idx % 400;
        int jj  = r / 80;
        int r2  = r % 80;
        int q   = r2 / 16;
        int r3  = r2 % 16;
        int sb  = r3 / 4;
        int e   = r3 % 4;
        int row = sb * 5 + jj;
        int k   = q * 4 + e;
        int oc  = 5 * (sb ^ (k / 5)) + (k % 5);
        const float* src = (m == 0) ? w_hh0 : (m == 1) ? w_ih1 :
                           (m == 2) ? w_hh1 : (m == 3) ? w_ih2 : w_hh2;
        wp[idx] = src[row * H + oc];
    }
    __syncthreads();

    const int lane = tid & 31;
    const int warp = tid >> 5;            // 0..3 -> SMSP 0..3
    const int gi   = lane >> 2;
    const int sub  = lane & 3;
    const int j0   = sub * 5;
    const int b0   = blockIdx.x * 64 + warp * 16 + gi;   // batch slot 0
    const int b1   = b0 + 8;                              // batch slot 1

    // lane's quad stream: quad (m,jj,q) at wz[(m*25 + jj*5 + q)*4]
    const ulonglong2* wz = (const ulonglong2*)wp + sub;

    float bias0[5], bias1[5], bias2[5], wih0r[5];
#pragma unroll
    for (int jj = 0; jj < 5; jj++) {
        int j = j0 + jj;
        bias0[jj] = b_ih0[j] + b_hh0[j];
        bias1[jj] = b_ih1[j] + b_hh1[j];
        bias2[jj] = b_ih2[j] + b_hh2[j];
        wih0r[jj] = w_ih0[j];
    }

    const float* xrow0 = x + (size_t)b0 * TSTEPS;
    const float* xrow1 = x + (size_t)b1 * TSTEPS;

    // persistent state (registers only; exchanged via 4-lane butterfly shfl)
    u64 hp0[2][10], hp1[2][10];   // gathered h0, h1 (k-pair packed, per-lane order)
    float h2own[2][5];            // own 5 rows of h2
#pragma unroll
    for (int q = 0; q < 10; q++) { hp0[0][q] = 0; hp0[1][q] = 0; hp1[0][q] = 0; hp1[1][q] = 0; }
#pragma unroll
    for (int jj = 0; jj < 5; jj++) { h2own[0][jj] = 0.f; h2own[1][jj] = 0.f; }

    float4 xq0 = make_float4(0.f,0.f,0.f,0.f), xq1 = xq0;

#pragma unroll 1
    for (int t = 0; t < TSTEPS; t++) {
        if ((t & 3) == 0) {
            xq0 = __ldg((const float4*)(xrow0 + t));
            xq1 = __ldg((const float4*)(xrow1 + t));
        }
        const int ph = t & 3;
        const float xv0 = (ph == 0) ? xq0.x : (ph == 1) ? xq0.y : (ph == 2) ? xq0.z : xq0.w;
        const float xv1 = (ph == 0) ? xq1.x : (ph == 1) ? xq1.y : (ph == 2) ? xq1.z : xq1.w;

        // ===== Layer 0: h0' = tanh(x*wih0 + bias0 + whh0 @ h0) =====
        float h0n0[5], h0n1[5];
        {
            u64 a0[5], a1[5];
#pragma unroll
            for (int jj = 0; jj < 5; jj++) {
                a0[jj] = pack2(fmaf(xv0, wih0r[jj], bias0[jj]), 0.f);
                a1[jj] = pack2(fmaf(xv1, wih0r[jj], bias0[jj]), 0.f);
            }
#pragma unroll
            for (int q = 0; q < 5; q++) {
#pragma unroll
                for (int jj = 0; jj < 5; jj++) {
                    ulonglong2 wv = wz[(jj * 5 + q) * 4];                  // m0
                    ffma2(a0[jj], hp0[0][2*q],   wv.x);
                    ffma2(a0[jj], hp0[0][2*q+1], wv.y);
                    ffma2(a1[jj], hp0[1][2*q],   wv.x);
                    ffma2(a1[jj], hp0[1][2*q+1], wv.y);
                }
            }
#pragma unroll
            for (int jj = 0; jj < 5; jj++) {
                float2 p0 = unpack2(a0[jj]); h0n0[jj] = tanh_fast(p0.x + p0.y);
                float2 p1 = unpack2(a1[jj]); h0n1[jj] = tanh_fast(p1.x + p1.y);
            }
        }
        // gather h0' into per-lane packed order
        {
            float a[10], b[10];
#pragma unroll
            for (int i = 0; i < 5; i++) {
                a[i] = h0n0[i];  a[5+i] = __shfl_xor_sync(0xffffffffu, h0n0[i], 1);
                b[i] = h0n1[i];  b[5+i] = __shfl_xor_sync(0xffffffffu, h0n1[i], 1);
            }
#pragma unroll
            for (int q = 0; q < 5; q++) {
                hp0[0][q] = pack2(a[2*q], a[2*q+1]);
                hp0[1][q] = pack2(b[2*q], b[2*q+1]);
            }
            float a2[10], b2[10];
#pragma unroll
            for (int i = 0; i < 10; i++) {
                a2[i] = __shfl_xor_sync(0xffffffffu, a[i], 2);
                b2[i] = __shfl_xor_sync(0xffffffffu, b[i], 2);
            }
#pragma unroll
            for (int q = 0; q < 5; q++) {
                hp0[0][5+q] = pack2(a2[2*q], a2[2*q+1]);
                hp0[1][5+q] = pack2(b2[2*q], b2[2*q+1]);
            }
        }

        // ===== Layer 1: h1' = tanh(wih1 @ h0' + bias1 + whh1 @ h1) =====
        float h1n0[5], h1n1[5];
        {
            u64 a0[5], a1[5];
#pragma unroll
            for (int jj = 0; jj < 5; jj++) { a0[jj] = pack2(bias1[jj], 0.f); a1[jj] = pack2(bias1[jj], 0.f); }
#pragma unroll
            for (int q = 0; q < 5; q++) {
#pragma unroll
                for (int jj = 0; jj < 5; jj++) {
                    ulonglong2 wiv = wz[100 + (jj * 5 + q) * 4];           // m1
                    ulonglong2 whv = wz[200 + (jj * 5 + q) * 4];           // m2
                    ffma2(a0[jj], hp0[0][2*q],   wiv.x);
                    ffma2(a0[jj], hp0[0][2*q+1], wiv.y);
                    ffma2(a0[jj], hp1[0][2*q],   whv.x);
                    ffma2(a0[jj], hp1[0][2*q+1], whv.y);
                    ffma2(a1[jj], hp0[1][2*q],   wiv.x);
                    ffma2(a1[jj], hp0[1][2*q+1], wiv.y);
                    ffma2(a1[jj], hp1[1][2*q],   whv.x);
                    ffma2(a1[jj], hp1[1][2*q+1], whv.y);
                }
            }
#pragma unroll
            for (int jj = 0; jj < 5; jj++) {
                float2 p0 = unpack2(a0[jj]); h1n0[jj] = tanh_fast(p0.x + p0.y);
                float2 p1 = unpack2(a1[jj]); h1n1[jj] = tanh_fast(p1.x + p1.y);
            }
        }
        // gather h1'
        {
            float a[10], b[10];
#pragma unroll
            for (int i = 0; i < 5; i++) {
                a[i] = h1n0[i];  a[5+i] = __shfl_xor_sync(0xffffffffu, h1n0[i], 1);
                b[i] = h1n1[i];  b[5+i] = __shfl_xor_sync(0xffffffffu, h1n1[i], 1);
            }
#pragma unroll
            for (int q = 0; q < 5; q++) {
                hp1[0][q] = pack2(a[2*q], a[2*q+1]);
                hp1[1][q] = pack2(b[2*q], b[2*q+1]);
            }
            float a2[10], b2[10];
#pragma unroll
            for (int i = 0; i < 10; i++) {
                a2[i] = __shfl_xor_sync(0xffffffffu, a[i], 2);
                b2[i] = __shfl_xor_sync(0xffffffffu, b[i], 2);
            }
#pragma unroll
            for (int q = 0; q < 5; q++) {
                hp1[0][5+q] = pack2(a2[2*q], a2[2*q+1]);
                hp1[1][5+q] = pack2(b2[2*q], b2[2*q+1]);
            }
        }

        // ===== Layer 2: h2' = tanh(wih2 @ h1' + bias2 + whh2 @ h2) =====
        {
            // gather h2 (own -> packed)
            u64 hp2a[10], hp2b[10];
            {
                float a[10], b[10];
#pragma unroll
                for (int i = 0; i < 5; i++) {
                    a[i] = h2own[0][i];  a[5+i] = __shfl_xor_sync(0xffffffffu, h2own[0][i], 1);
                    b[i] = h2own[1][i];  b[5+i] = __shfl_xor_sync(0xffffffffu, h2own[1][i], 1);
                }
#pragma unroll
                for (int q = 0; q < 5; q++) {
                    hp2a[q] = pack2(a[2*q], a[2*q+1]);
                    hp2b[q] = pack2(b[2*q], b[2*q+1]);
                }
                float a2[10], b2[10];
#pragma unroll
                for (int i = 0; i < 10; i++) {
                    a2[i] = __shfl_xor_sync(0xffffffffu, a[i], 2);
                    b2[i] = __shfl_xor_sync(0xffffffffu, b[i], 2);
                }
#pragma unroll
                for (int q = 0; q < 5; q++) {
                    hp2a[5+q] = pack2(a2[2*q], a2[2*q+1]);
                    hp2b[5+q] = pack2(b2[2*q], b2[2*q+1]);
                }
            }
            u64 a0[5], a1[5];
#pragma unroll
            for (int jj = 0; jj < 5; jj++) { a0[jj] = pack2(bias2[jj], 0.f); a1[jj] = pack2(bias2[jj], 0.f); }
#pragma unroll
            for (int q = 0; q < 5; q++) {
#pragma unroll
                for (int jj = 0; jj < 5; jj++) {
                    ulonglong2 wiv = wz[300 + (jj * 5 + q) * 4];           // m3
                    ulonglong2 whv = wz[400 + (jj * 5 + q) * 4];           // m4
                    ffma2(a0[jj], hp1[0][2*q],   wiv.x);
                    ffma2(a0[jj], hp1[0][2*q+1], wiv.y);
                    ffma2(a0[jj], hp2a[2*q],     whv.x);
                    ffma2(a0[jj], hp2a[2*q+1],   whv.y);
                    ffma2(a1[jj], hp1[1][2*q],   wiv.x);
                    ffma2(a1[jj], hp1[1][2*q+1], wiv.y);
                    ffma2(a1[jj], hp2b[2*q],     whv.x);
                    ffma2(a1[jj], hp2b[2*q+1],   whv.y);
                }
            }
#pragma unroll
            for (int jj = 0; jj < 5; jj++) {
                float2 p0 = unpack2(a0[jj]); h2own[0][jj] = tanh_fast(p0.x + p0.y);
                float2 p1 = unpack2(a1[jj]); h2own[1][jj] = tanh_fast(p1.x + p1.y);
            }
        }
    }

    // ===== FC epilogue: out[b] = h2 . fc_w + fc_b =====
    float s0 = 0.f, s1 = 0.f;
#pragma unroll
    for (int jj = 0; jj < 5; jj++) {
        float w = __ldg(&fc_w[j0 + jj]);
        s0 += h2own[0][jj] * w;
        s1 += h2own[1][jj] * w;
    }
    s0 += __shfl_xor_sync(0xffffffffu, s0, 1);
    s0 += __shfl_xor_sync(0xffffffffu, s0, 2);
    s1 += __shfl_xor_sync(0xffffffffu, s1, 1);
    s1 += __shfl_xor_sync(0xffffffffu, s1, 2);
    if (sub == 0) {
        float fb = __ldg(&fc_b[0]);
        out[b0] = s0 + fb;
        out[b1] = s1 + fb;
    }
}

extern "C" void kernel_launch(void* const* d_in, const int* in_sizes, int n_in,
                              void* d_out, int out_size) {
    (void)in_sizes; (void)n_in; (void)out_size;
    rnn3_kernel<<<NBLOCKS, NTHREADS>>>(
        (const float*)d_in[0],
        (const float*)d_in[1],  (const float*)d_in[2],
        (const float*)d_in[3],  (const float*)d_in[4],
        (const float*)d_in[5],  (const float*)d_in[6],
        (const float*)d_in[7],  (const float*)d_in[8],
        (const float*)d_in[9],  (const float*)d_in[10],
        (const float*)d_in[11], (const float*)d_in[12],
        (const float*)d_in[13], (const float*)d_in[14],
        (float*)d_out);
}

// round 17
// speedup vs baseline: 1.1669x; 1.0468x over previous
#include <cuda_runtime.h>
#include <cstdint>

#define TSTEPS 512
#define H 20
#define NTHREADS 128    // 4 warps -> one per SMSP (wid%4)
#define NBLOCKS 128     // 128 blocks * 64 batches = 8192; 1 block/SM, balanced
#define W0_REG_QUADS 16 // m0 quads held in registers (of 25); 64 regs

typedef unsigned long long u64;

__device__ __forceinline__ void ffma2(u64& acc, u64 a, u64 b) {
    asm("fma.rn.f32x2 %0, %1, %2, %0;" : "+l"(acc) : "l"(a), "l"(b));
}
__device__ __forceinline__ u64 pack2(float lo, float hi) {
    u64 r; asm("mov.b64 %0, {%1, %2};" : "=l"(r) : "f"(lo), "f"(hi)); return r;
}
__device__ __forceinline__ float2 unpack2(u64 v) {
    float2 r; asm("mov.b64 {%0, %1}, %2;" : "=f"(r.x), "=f"(r.y) : "l"(v)); return r;
}
// 5-op tanh: 1 - 2/(e^{2x}+1). ex2.approx+rcp.approx, abs err ~1e-7.
__device__ __forceinline__ float tanh_fast(float x) {
    float e;
    asm("ex2.approx.f32 %0, %1;" : "=f"(e) : "f"(x * 2.8853900817779268f));
    float rr;
    asm("rcp.approx.f32 %0, %1;" : "=f"(rr) : "f"(e + 1.0f));
    return fmaf(-2.0f, rr, 1.0f);
}

// Direct single-stage 4-lane all-gather: blocks b=0..3 of the packed order
// [sub, sub^1, sub^2, sub^3] come from three INDEPENDENT shfl.xor sets
// (masks 1,2,3) -> chain latency 26 cy instead of 52. Same 15 shfl.
__device__ __forceinline__ void gather20(const float v[5], u64 hp[10]) {
    float f[20];
#pragma unroll
    for (int i = 0; i < 5; i++) {
        f[i]      = v[i];
        f[5 + i]  = __shfl_xor_sync(0xffffffffu, v[i], 1);
        f[10 + i] = __shfl_xor_sync(0xffffffffu, v[i], 2);
        f[15 + i] = __shfl_xor_sync(0xffffffffu, v[i], 3);
    }
#pragma unroll
    for (int q = 0; q < 10; q++) hp[q] = pack2(f[2 * q], f[2 * q + 1]);
}

__global__ __launch_bounds__(NTHREADS)
void rnn3_kernel(
    const float* __restrict__ x,
    const float* __restrict__ w_ih0, const float* __restrict__ w_hh0,
    const float* __restrict__ b_ih0, const float* __restrict__ b_hh0,
    const float* __restrict__ w_ih1, const float* __restrict__ w_hh1,
    const float* __restrict__ b_ih1, const float* __restrict__ b_hh1,
    const float* __restrict__ w_ih2, const float* __restrict__ w_hh2,
    const float* __restrict__ b_ih2, const float* __restrict__ b_hh2,
    const float* __restrict__ fc_w, const float* __restrict__ fc_b,
    float* __restrict__ out)
{
    // Quad-interleaved permuted weights (R15 layout):
    //   wp[ ((m*5 + jj)*5 + q)*16 + sub*4 + e ]
    //     = W_m[ sub*5 + jj ][ 5*(sub ^ (k/5)) + k%5 ],  k = 4q + e
    // m: 0=w_hh0 1=w_ih1 2=w_hh1 3=w_ih2 4=w_hh2.  8 KB total.
    __shared__ __align__(16) float wp[2000];

    const int tid = threadIdx.x;
    for (int idx = tid; idx < 2000; idx += NTHREADS) {
        int m   = idx / 400;
        int r   = idx % 400;
        int jj  = r / 80;
        int r2  = r % 80;
        int q   = r2 / 16;
        int r3  = r2 % 16;
        int sb  = r3 / 4;
        int e   = r3 % 4;
        int row = sb * 5 + jj;
        int k   = q * 4 + e;
        int oc  = 5 * (sb ^ (k / 5)) + (k % 5);
        const float* src = (m == 0) ? w_hh0 : (m == 1) ? w_ih1 :
                           (m == 2) ? w_hh1 : (m == 3) ? w_ih2 : w_hh2;
        wp[idx] = src[row * H + oc];
    }
    __syncthreads();

    const int lane = tid & 31;
    const int warp = tid >> 5;            // 0..3 -> SMSP 0..3
    const int gi   = lane >> 2;
    const int sub  = lane & 3;
    const int j0   = sub * 5;
    const int b0   = blockIdx.x * 64 + warp * 16 + gi;   // batch slot 0
    const int b1   = b0 + 8;                              // batch slot 1

    // lane's quad stream: quad (m,jj,q) at wz[(m*25 + jj*5 + q)*4]
    const ulonglong2* wz = (const ulonglong2*)wp + sub;

    // m0 weight slice in REGISTERS (loop-invariant; kills 16 LDS.128/step)
    ulonglong2 w0r[W0_REG_QUADS];
#pragma unroll
    for (int i = 0; i < W0_REG_QUADS; i++) w0r[i] = wz[i * 4];

    float bias0[5], bias1[5], bias2[5], wih0r[5];
#pragma unroll
    for (int jj = 0; jj < 5; jj++) {
        int j = j0 + jj;
        bias0[jj] = b_ih0[j] + b_hh0[j];
        bias1[jj] = b_ih1[j] + b_hh1[j];
        bias2[jj] = b_ih2[j] + b_hh2[j];
        wih0r[jj] = w_ih0[j];
    }

    const float* xrow0 = x + (size_t)b0 * TSTEPS;
    const float* xrow1 = x + (size_t)b1 * TSTEPS;

    // persistent state (registers only; exchanged via 4-lane shfl)
    u64 hp0[2][10], hp1[2][10];   // gathered h0, h1 (k-pair packed, per-lane order)
    float h2own[2][5];            // own 5 rows of h2
#pragma unroll
    for (int q = 0; q < 10; q++) { hp0[0][q] = 0; hp0[1][q] = 0; hp1[0][q] = 0; hp1[1][q] = 0; }
#pragma unroll
    for (int jj = 0; jj < 5; jj++) { h2own[0][jj] = 0.f; h2own[1][jj] = 0.f; }

    float4 xq0 = make_float4(0.f,0.f,0.f,0.f), xq1 = xq0;

#pragma unroll 1
    for (int t = 0; t < TSTEPS; t++) {
        if ((t & 3) == 0) {
            xq0 = __ldg((const float4*)(xrow0 + t));
            xq1 = __ldg((const float4*)(xrow1 + t));
        }
        const int ph = t & 3;
        const float xv0 = (ph == 0) ? xq0.x : (ph == 1) ? xq0.y : (ph == 2) ? xq0.z : xq0.w;
        const float xv1 = (ph == 0) ? xq1.x : (ph == 1) ? xq1.y : (ph == 2) ? xq1.z : xq1.w;

        // ===== Layer 0: h0' = tanh(x*wih0 + bias0 + whh0 @ h0) =====
        float h0n0[5], h0n1[5];
        {
            u64 a0[5], a1[5];
#pragma unroll
            for (int jj = 0; jj < 5; jj++) {
                a0[jj] = pack2(fmaf(xv0, wih0r[jj], bias0[jj]), 0.f);
                a1[jj] = pack2(fmaf(xv1, wih0r[jj], bias0[jj]), 0.f);
            }
#pragma unroll
            for (int q = 0; q < 5; q++) {
#pragma unroll
                for (int jj = 0; jj < 5; jj++) {
                    const int qi = jj * 5 + q;        // constant after unroll
                    ulonglong2 wv;
                    if (qi < W0_REG_QUADS) wv = w0r[qi];      // registers
                    else                   wv = wz[qi * 4];   // smem (m0 tail)
                    ffma2(a0[jj], hp0[0][2*q],   wv.x);
                    ffma2(a0[jj], hp0[0][2*q+1], wv.y);
                    ffma2(a1[jj], hp0[1][2*q],   wv.x);
                    ffma2(a1[jj], hp0[1][2*q+1], wv.y);
                }
            }
#pragma unroll
            for (int jj = 0; jj < 5; jj++) {
                float2 p0 = unpack2(a0[jj]); h0n0[jj] = tanh_fast(p0.x + p0.y);
                float2 p1 = unpack2(a1[jj]); h0n1[jj] = tanh_fast(p1.x + p1.y);
            }
        }
        gather20(h0n0, hp0[0]);
        gather20(h0n1, hp0[1]);

        // ===== Layer 1: h1' = tanh(wih1 @ h0' + bias1 + whh1 @ h1) =====
        float h1n0[5], h1n1[5];
        {
            u64 a0[5], a1[5];
#pragma unroll
            for (int jj = 0; jj < 5; jj++) { a0[jj] = pack2(bias1[jj], 0.f); a1[jj] = pack2(bias1[jj], 0.f); }
#pragma unroll
            for (int q = 0; q < 5; q++) {
#pragma unroll
                for (int jj = 0; jj < 5; jj++) {
                    ulonglong2 wiv = wz[100 + (jj * 5 + q) * 4];           // m1
                    ulonglong2 whv = wz[200 + (jj * 5 + q) * 4];           // m2
                    ffma2(a0[jj], hp0[0][2*q],   wiv.x);
                    ffma2(a0[jj], hp0[0][2*q+1], wiv.y);
                    ffma2(a0[jj], hp1[0][2*q],   whv.x);
                    ffma2(a0[jj], hp1[0][2*q+1], whv.y);
                    ffma2(a1[jj], hp0[1][2*q],   wiv.x);
                    ffma2(a1[jj], hp0[1][2*q+1], wiv.y);
                    ffma2(a1[jj], hp1[1][2*q],   whv.x);
                    ffma2(a1[jj], hp1[1][2*q+1], whv.y);
                }
            }
#pragma unroll
            for (int jj = 0; jj < 5; jj++) {
                float2 p0 = unpack2(a0[jj]); h1n0[jj] = tanh_fast(p0.x + p0.y);
                float2 p1 = unpack2(a1[jj]); h1n1[jj] = tanh_fast(p1.x + p1.y);
            }
        }
        gather20(h1n0, hp1[0]);
        gather20(h1n1, hp1[1]);

        // ===== Layer 2: h2' = tanh(wih2 @ h1' + bias2 + whh2 @ h2) =====
        {
            u64 hp2a[10], hp2b[10];
            gather20(h2own[0], hp2a);
            gather20(h2own[1], hp2b);
            u64 a0[5], a1[5];
#pragma unroll
            for (int jj = 0; jj < 5; jj++) { a0[jj] = pack2(bias2[jj], 0.f); a1[jj] = pack2(bias2[jj], 0.f); }
#pragma unroll
            for (int q = 0; q < 5; q++) {
#pragma unroll
                for (int jj = 0; jj < 5; jj++) {
                    ulonglong2 wiv = wz[300 + (jj * 5 + q) * 4];           // m3
                    ulonglong2 whv = wz[400 + (jj * 5 + q) * 4];           // m4
                    ffma2(a0[jj], hp1[0][2*q],   wiv.x);
                    ffma2(a0[jj], hp1[0][2*q+1], wiv.y);
                    ffma2(a0[jj], hp2a[2*q],     whv.x);
                    ffma2(a0[jj], hp2a[2*q+1],   whv.y);
                    ffma2(a1[jj], hp1[1][2*q],   wiv.x);
                    ffma2(a1[jj], hp1[1][2*q+1], wiv.y);
                    ffma2(a1[jj], hp2b[2*q],     whv.x);
                    ffma2(a1[jj], hp2b[2*q+1],   whv.y);
                }
            }
#pragma unroll
            for (int jj = 0; jj < 5; jj++) {
                float2 p0 = unpack2(a0[jj]); h2own[0][jj] = tanh_fast(p0.x + p0.y);
                float2 p1 = unpack2(a1[jj]); h2own[1][jj] = tanh_fast(p1.x + p1.y);
            }
        }
    }

    // ===== FC epilogue: out[b] = h2 . fc_w + fc_b =====
    float s0 = 0.f, s1 = 0.f;
#pragma unroll
    for (int jj = 0; jj < 5; jj++) {
        float w = __ldg(&fc_w[j0 + jj]);
        s0 += h2own[0][jj] * w;
        s1 += h2own[1][jj] * w;
    }
    s0 += __shfl_xor_sync(0xffffffffu, s0, 1);
    s0 += __shfl_xor_sync(0xffffffffu, s0, 2);
    s1 += __shfl_xor_sync(0xffffffffu, s1, 1);
    s1 += __shfl_xor_sync(0xffffffffu, s1, 2);
    if (sub == 0) {
        float fb = __ldg(&fc_b[0]);
        out[b0] = s0 + fb;
        out[b1] = s1 + fb;
    }
}

extern "C" void kernel_launch(void* const* d_in, const int* in_sizes, int n_in,
                              void* d_out, int out_size) {
    (void)in_sizes; (void)n_in; (void)out_size;
    rnn3_kernel<<<NBLOCKS, NTHREADS>>>(
        (const float*)d_in[0],
        (const float*)d_in[1],  (const float*)d_in[2],
        (const float*)d_in[3],  (const float*)d_in[4],
        (const float*)d_in[5],  (const float*)d_in[6],
        (const float*)d_in[7],  (const float*)d_in[8],
        (const float*)d_in[9],  (const float*)d_in[10],
        (const float*)d_in[11], (const float*)d_in[12],
        (const float*)d_in[13], (const float*)d_in[14],
        (float*)d_out);
}